// round 9
// baseline (speedup 1.0000x reference)
#include <cuda_runtime.h>
#include <cstdint>

// out = sum_{b, k != labels[b]} exp( -||inputs[b,:] - decoded[b,k,:]||^2 )
// B=4096, K=64, DIM=512, fp32. Pure HBM stream over decoded (512 MiB).
//
// Grid = 32768 CTAs x 64 threads: eighth of a batch row per CTA (2 warps x
// 4 k-rows). Identical warp body to the best kernel (R8): pure LDG+FMA hot
// loop, per-lane per-row accumulators, 2-row rotating prefetch (8 LDG.128
// in flight), all shuffles/exp deferred to epilogue. The only change is CTA
// granularity: 8 KB stream per CTA halves the final-wave raggedness.

#define B_    4096
#define K_    64
#define DIM_  512

__global__ void init_kernel(float* out) {
    if (threadIdx.x == 0) out[0] = 0.0f;
}

__global__ __launch_bounds__(64)
void mse_exp_loss_kernel(const float* __restrict__ inputs,
                         const float* __restrict__ decoded,
                         const long long* __restrict__ labels,
                         float* __restrict__ out) {
    const int b    = blockIdx.x >> 3;           // 8 CTAs per batch row
    const int oct  = blockIdx.x & 7;
    const int warp = threadIdx.x >> 5;          // 0..1
    const int lane = threadIdx.x & 31;
    const int k0   = oct * 8 + warp * 4;        // this warp's 4 k-rows

    const float4* dbase = reinterpret_cast<const float4*>(
        decoded + ((size_t)b * K_ + k0) * DIM_);

    // issue first row-pair's streaming loads before anything else
    float4 d0[4], d1[4];
    #pragma unroll
    for (int i = 0; i < 4; i++) d0[i] = __ldcs(&dbase[             lane + i * 32]);
    #pragma unroll
    for (int i = 0; i < 4; i++) d1[i] = __ldcs(&dbase[(DIM_ / 4) + lane + i * 32]);

    const int lbl = (int)__ldg(&labels[b]);

    // stage inputs[b] in registers (16 floats/lane, reused for 4 rows;
    // served from L2 — inputs is only 8 MiB)
    const float4* inrow = reinterpret_cast<const float4*>(
        inputs + (size_t)b * DIM_);
    float4 x[4];
    #pragma unroll
    for (int i = 0; i < 4; i++) x[i] = __ldg(&inrow[lane + i * 32]);

    // per-lane partial squared distance for each of this warp's 4 rows
    float s[4];
    #pragma unroll
    for (int r = 0; r < 4; r++) s[r] = 0.0f;

    #pragma unroll
    for (int kk = 0; kk < 4; kk += 2) {
        // prefetch next row pair while current pair is consumed below
        float4 n0[4], n1[4];
        if (kk + 2 < 4) {
            const float4* p0 = dbase + (kk + 2) * (DIM_ / 4);
            const float4* p1 = dbase + (kk + 3) * (DIM_ / 4);
            #pragma unroll
            for (int i = 0; i < 4; i++) n0[i] = __ldcs(&p0[lane + i * 32]);
            #pragma unroll
            for (int i = 0; i < 4; i++) n1[i] = __ldcs(&p1[lane + i * 32]);
        }

        // pure FMA consumption — no shuffles, no exp, in the hot loop
        #pragma unroll
        for (int i = 0; i < 4; i++) {
            float e;
            e = x[i].x - d0[i].x; s[kk]     = fmaf(e, e, s[kk]);
            e = x[i].y - d0[i].y; s[kk]     = fmaf(e, e, s[kk]);
            e = x[i].z - d0[i].z; s[kk]     = fmaf(e, e, s[kk]);
            e = x[i].w - d0[i].w; s[kk]     = fmaf(e, e, s[kk]);
            e = x[i].x - d1[i].x; s[kk + 1] = fmaf(e, e, s[kk + 1]);
            e = x[i].y - d1[i].y; s[kk + 1] = fmaf(e, e, s[kk + 1]);
            e = x[i].z - d1[i].z; s[kk + 1] = fmaf(e, e, s[kk + 1]);
            e = x[i].w - d1[i].w; s[kk + 1] = fmaf(e, e, s[kk + 1]);
        }

        if (kk + 2 < 4) {
            #pragma unroll
            for (int i = 0; i < 4; i++) { d0[i] = n0[i]; d1[i] = n1[i]; }
        }
    }

    // epilogue: reduce 4 rows (pairwise-interleaved butterflies so the two
    // chains overlap), apply label mask + exp, single guarded atomic.
    float acc = 0.0f;
    #pragma unroll
    for (int r = 0; r < 4; r += 2) {
        float a = s[r], c = s[r + 1];
        #pragma unroll
        for (int o = 16; o > 0; o >>= 1) {
            a += __shfl_xor_sync(0xFFFFFFFFu, a, o);
            c += __shfl_xor_sync(0xFFFFFFFFu, c, o);
        }
        if (lane == 0) {
            if (k0 + r     != lbl) acc += __expf(-a);
            if (k0 + r + 1 != lbl) acc += __expf(-c);
        }
    }

    // exp(-s) with s ~ 1024 underflows to +0; skipping a +0 add is exact and
    // avoids same-address L2 atomics bunching at the end.
    if (lane == 0 && acc != 0.0f)
        atomicAdd(out, acc);
}

extern "C" void kernel_launch(void* const* d_in, const int* in_sizes, int n_in,
                              void* d_out, int out_size) {
    const float*     inputs  = (const float*)d_in[0];
    const float*     decoded = (const float*)d_in[1];
    const long long* labels  = (const long long*)d_in[2];
    float* out = (float*)d_out;

    init_kernel<<<1, 32>>>(out);
    mse_exp_loss_kernel<<<B_ * 8, 64>>>(inputs, decoded, labels, out);
}

// round 10
// speedup vs baseline: 1.0008x; 1.0008x over previous
#include <cuda_runtime.h>
#include <cstdint>

// out = sum_{b, k != labels[b]} exp( -||inputs[b,:] - decoded[b,k,:]||^2 )
// B=4096, K=64, DIM=512, fp32. Pure HBM stream over decoded (512 MiB).
//
// Grid = 32768 CTAs x 64 threads (eighth of a batch row per CTA, 2 warps x
// 4 k-rows). Change vs best (R9): ALL 16 LDG.128 for the warp's 4 rows are
// issued back-to-back at warp start (one contiguous 8 KB burst, MLP_p1=16),
// eliminating the mid-CTA load-issue bubble of the rotating prefetch and
// the loadless final-pair consume phase. Shuffles/exp stay in the epilogue.

#define B_    4096
#define K_    64
#define DIM_  512

__global__ void init_kernel(float* out) {
    if (threadIdx.x == 0) out[0] = 0.0f;
}

__global__ __launch_bounds__(64)
void mse_exp_loss_kernel(const float* __restrict__ inputs,
                         const float* __restrict__ decoded,
                         const long long* __restrict__ labels,
                         float* __restrict__ out) {
    const int b    = blockIdx.x >> 3;           // 8 CTAs per batch row
    const int oct  = blockIdx.x & 7;
    const int warp = threadIdx.x >> 5;          // 0..1
    const int lane = threadIdx.x & 31;
    const int k0   = oct * 8 + warp * 4;        // this warp's 4 k-rows

    const float4* dbase = reinterpret_cast<const float4*>(
        decoded + ((size_t)b * K_ + k0) * DIM_);

    // issue ALL 16 streaming loads (4 rows x 4 float4/lane) back-to-back
    // before anything else touches memory — one 8 KB burst per warp.
    float4 d[4][4];
    #pragma unroll
    for (int r = 0; r < 4; r++) {
        const float4* row = dbase + r * (DIM_ / 4);
        #pragma unroll
        for (int i = 0; i < 4; i++)
            d[r][i] = __ldcs(&row[lane + i * 32]);
    }

    const int lbl = (int)__ldg(&labels[b]);

    // stage inputs[b] in registers (16 floats/lane; served from L2 —
    // inputs is only 8 MiB and hot)
    const float4* inrow = reinterpret_cast<const float4*>(
        inputs + (size_t)b * DIM_);
    float4 x[4];
    #pragma unroll
    for (int i = 0; i < 4; i++) x[i] = __ldg(&inrow[lane + i * 32]);

    // per-lane partial squared distance for each of this warp's 4 rows
    float s[4];
    #pragma unroll
    for (int r = 0; r < 4; r++) s[r] = 0.0f;

    #pragma unroll
    for (int r = 0; r < 4; r++) {
        #pragma unroll
        for (int i = 0; i < 4; i++) {
            float e;
            e = x[i].x - d[r][i].x; s[r] = fmaf(e, e, s[r]);
            e = x[i].y - d[r][i].y; s[r] = fmaf(e, e, s[r]);
            e = x[i].z - d[r][i].z; s[r] = fmaf(e, e, s[r]);
            e = x[i].w - d[r][i].w; s[r] = fmaf(e, e, s[r]);
        }
    }

    // epilogue: reduce 4 rows (pairwise-interleaved butterflies so the two
    // chains overlap), apply label mask + exp, single guarded atomic.
    float acc = 0.0f;
    #pragma unroll
    for (int r = 0; r < 4; r += 2) {
        float a = s[r], c = s[r + 1];
        #pragma unroll
        for (int o = 16; o > 0; o >>= 1) {
            a += __shfl_xor_sync(0xFFFFFFFFu, a, o);
            c += __shfl_xor_sync(0xFFFFFFFFu, c, o);
        }
        if (lane == 0) {
            if (k0 + r     != lbl) acc += __expf(-a);
            if (k0 + r + 1 != lbl) acc += __expf(-c);
        }
    }

    // exp(-s) with s ~ 1024 underflows to +0; skipping a +0 add is exact and
    // avoids same-address L2 atomics bunching at the end.
    if (lane == 0 && acc != 0.0f)
        atomicAdd(out, acc);
}

extern "C" void kernel_launch(void* const* d_in, const int* in_sizes, int n_in,
                              void* d_out, int out_size) {
    const float*     inputs  = (const float*)d_in[0];
    const float*     decoded = (const float*)d_in[1];
    const long long* labels  = (const long long*)d_in[2];
    float* out = (float*)d_out;

    init_kernel<<<1, 32>>>(out);
    mse_exp_loss_kernel<<<B_ * 8, 64>>>(inputs, decoded, labels, out);
}